// round 6
// baseline (speedup 1.0000x reference)
#include <cuda_runtime.h>
#include <math.h>

#define C_DIM 512
#define AREA  4096
#define BATCH 4
#define GROUPS 32
#define CPG   16
#define GRP_F4 16384   // (CPG*AREA)/4 float4s per group

// ---------------- scratch (static device globals; no allocation) ----------------
__device__ float g_xn  [(size_t)BATCH * C_DIM * AREA];
__device__ float g_q   [(size_t)BATCH * C_DIM * AREA];
__device__ float g_k   [(size_t)BATCH * C_DIM * AREA];
__device__ float g_v   [(size_t)BATCH * C_DIM * AREA];
__device__ float g_ao  [(size_t)BATCH * C_DIM * AREA];
__device__ float g_attn[(size_t)BATCH * AREA * AREA];

// ---------------- GroupNorm ----------------
// One block per (batch, group). Group = 16 channels x 4096 pixels = 65536 floats.
__global__ void groupnorm_kernel(const float* __restrict__ net,
                                 const float* __restrict__ gscale,
                                 const float* __restrict__ gbias,
                                 float* __restrict__ xn) {
    const int bg = blockIdx.x;          // 0..127
    const int b  = bg >> 5;
    const int g  = bg & 31;
    const size_t base = ((size_t)b * C_DIM + (size_t)g * CPG) * AREA;
    const float4* src4 = (const float4*)(net + base);
    float4* dst4 = (float4*)(xn + base);
    const int tid = threadIdx.x;

    float s = 0.f, ss = 0.f;
    for (int i = tid; i < GRP_F4; i += 256) {
        float4 v = src4[i];
        s  += v.x + v.y + v.z + v.w;
        ss += v.x*v.x + v.y*v.y + v.z*v.z + v.w*v.w;
    }
    __shared__ float red[512];
    red[tid] = s; red[256 + tid] = ss;
    __syncthreads();
    for (int off = 128; off > 0; off >>= 1) {
        if (tid < off) {
            red[tid]       += red[tid + off];
            red[256 + tid] += red[256 + tid + off];
        }
        __syncthreads();
    }
    const float inv_n = 1.0f / 65536.0f;
    const float mu   = red[0] * inv_n;
    const float var  = red[256] * inv_n - mu * mu;
    const float rstd = rsqrtf(var + 1e-6f);

    for (int i = tid; i < GRP_F4; i += 256) {
        const int c_local = i >> 10;            // (i*4)/4096
        const float sc = gscale[g * CPG + c_local] * rstd;
        const float bi = gbias[g * CPG + c_local];
        float4 v = src4[i];
        v.x = (v.x - mu) * sc + bi;
        v.y = (v.y - mu) * sc + bi;
        v.z = (v.z - mu) * sc + bi;
        v.w = (v.w - mu) * sc + bi;
        dst4[i] = v;
    }
}

// ---------------- generic tiled fp32 GEMM ----------------
// C[m,n] = alpha * sum_k Aval(m,k)*Bval(k,n) + bias[m] + resid[m,n]
// TA=0: A row-major [M,K];  TA=1: A stored [K,M]
// TB=0: B row-major [K,N];  TB=1: B stored [N,K]
// Block tile 128x128, K-tile 16, 256 threads, 8x8 per thread.
// All of M,N,K are multiples of 128/16 in this problem (no bounds checks).
template<int TA, int TB>
__global__ __launch_bounds__(256, 2)
void gemm128(const float* __restrict__ A, const float* __restrict__ B,
             float* __restrict__ C,
             int M, int N, int K,
             size_t sAb, size_t sBb, size_t sCb,
             float alpha,
             const float* __restrict__ bias,
             const float* __restrict__ resid, size_t sRb) {
    __shared__ float As[16][132];
    __shared__ float Bs[16][132];

    const int tid = threadIdx.x;
    const int tn = tid & 15;
    const int tm = tid >> 4;
    const int n0 = blockIdx.x * 128;
    const int m0 = blockIdx.y * 128;
    const int bz = blockIdx.z;

    const float* Ab = A + (size_t)bz * sAb;
    const float* Bb = B + (size_t)bz * sBb;

    float acc[8][8];
    #pragma unroll
    for (int i = 0; i < 8; ++i)
        #pragma unroll
        for (int j = 0; j < 8; ++j) acc[i][j] = 0.f;

    for (int k0 = 0; k0 < K; k0 += 16) {
        #pragma unroll
        for (int l = tid; l < 2048; l += 256) {
            if (TA == 0) {
                const int kk = l & 15, mm = l >> 4;      // contiguous along k
                As[kk][mm] = Ab[(size_t)(m0 + mm) * K + (k0 + kk)];
            } else {
                const int mm = l & 127, kk = l >> 7;     // contiguous along m
                As[kk][mm] = Ab[(size_t)(k0 + kk) * M + (m0 + mm)];
            }
        }
        #pragma unroll
        for (int l = tid; l < 2048; l += 256) {
            if (TB == 0) {
                const int nn = l & 127, kk = l >> 7;     // contiguous along n
                Bs[kk][nn] = Bb[(size_t)(k0 + kk) * N + (n0 + nn)];
            } else {
                const int kk = l & 15, nn = l >> 4;      // contiguous along k
                Bs[kk][nn] = Bb[(size_t)(n0 + nn) * K + (k0 + kk)];
            }
        }
        __syncthreads();

        #pragma unroll
        for (int kk = 0; kk < 16; ++kk) {
            float a[8], bb[8];
            *(float4*)&a[0]  = *(const float4*)&As[kk][tm * 8];
            *(float4*)&a[4]  = *(const float4*)&As[kk][tm * 8 + 4];
            *(float4*)&bb[0] = *(const float4*)&Bs[kk][tn * 8];
            *(float4*)&bb[4] = *(const float4*)&Bs[kk][tn * 8 + 4];
            #pragma unroll
            for (int i = 0; i < 8; ++i)
                #pragma unroll
                for (int j = 0; j < 8; ++j)
                    acc[i][j] += a[i] * bb[j];
        }
        __syncthreads();
    }

    float* Cb = C + (size_t)bz * sCb;
    const float* Rb = resid ? (resid + (size_t)bz * sRb) : nullptr;

    #pragma unroll
    for (int i = 0; i < 8; ++i) {
        const int m = m0 + tm * 8 + i;
        const float bi = bias ? bias[m] : 0.f;
        const size_t off = (size_t)m * N + (n0 + tn * 8);
        float4 o0, o1;
        o0.x = alpha * acc[i][0] + bi; o0.y = alpha * acc[i][1] + bi;
        o0.z = alpha * acc[i][2] + bi; o0.w = alpha * acc[i][3] + bi;
        o1.x = alpha * acc[i][4] + bi; o1.y = alpha * acc[i][5] + bi;
        o1.z = alpha * acc[i][6] + bi; o1.w = alpha * acc[i][7] + bi;
        if (Rb) {
            float4 r0 = *(const float4*)&Rb[off];
            float4 r1 = *(const float4*)&Rb[off + 4];
            o0.x += r0.x; o0.y += r0.y; o0.z += r0.z; o0.w += r0.w;
            o1.x += r1.x; o1.y += r1.y; o1.z += r1.z; o1.w += r1.w;
        }
        *(float4*)&Cb[off]     = o0;
        *(float4*)&Cb[off + 4] = o1;
    }
}

// ---------------- softmax over rows of length 4096 (register-resident) ----------------
__global__ void softmax4096(float* __restrict__ attn) {
    const size_t row = blockIdx.x;          // 0 .. BATCH*AREA-1
    float* p = attn + row * AREA;
    const int tid = threadIdx.x;

    float4 r[4];
    #pragma unroll
    for (int i = 0; i < 4; ++i)
        r[i] = *(const float4*)&p[(tid + i * 256) * 4];

    float m = -3.0e38f;
    #pragma unroll
    for (int i = 0; i < 4; ++i) {
        m = fmaxf(m, fmaxf(fmaxf(r[i].x, r[i].y), fmaxf(r[i].z, r[i].w)));
    }
    __shared__ float red[256];
    red[tid] = m; __syncthreads();
    for (int off = 128; off > 0; off >>= 1) {
        if (tid < off) red[tid] = fmaxf(red[tid], red[tid + off]);
        __syncthreads();
    }
    m = red[0];
    __syncthreads();

    float s = 0.f;
    #pragma unroll
    for (int i = 0; i < 4; ++i) {
        r[i].x = __expf(r[i].x - m); r[i].y = __expf(r[i].y - m);
        r[i].z = __expf(r[i].z - m); r[i].w = __expf(r[i].w - m);
        s += r[i].x + r[i].y + r[i].z + r[i].w;
    }
    red[tid] = s; __syncthreads();
    for (int off = 128; off > 0; off >>= 1) {
        if (tid < off) red[tid] += red[tid + off];
        __syncthreads();
    }
    const float inv = 1.0f / red[0];

    #pragma unroll
    for (int i = 0; i < 4; ++i) {
        r[i].x *= inv; r[i].y *= inv; r[i].z *= inv; r[i].w *= inv;
        *(float4*)&p[(tid + i * 256) * 4] = r[i];
    }
}

// ---------------- launch ----------------
extern "C" void kernel_launch(void* const* d_in, const int* in_sizes, int n_in,
                              void* d_out, int out_size) {
    const float* net = (const float*)d_in[0];
    const float* gns = (const float*)d_in[1];
    const float* gnb = (const float*)d_in[2];
    const float* wq  = (const float*)d_in[3];
    const float* bq  = (const float*)d_in[4];
    const float* wk  = (const float*)d_in[5];
    const float* bk  = (const float*)d_in[6];
    const float* wv  = (const float*)d_in[7];
    const float* bv  = (const float*)d_in[8];
    const float* wo  = (const float*)d_in[9];
    const float* bo  = (const float*)d_in[10];
    float* out = (float*)d_out;

    float *xn, *q, *k, *v, *ao, *attn;
    cudaGetSymbolAddress((void**)&xn,   g_xn);
    cudaGetSymbolAddress((void**)&q,    g_q);
    cudaGetSymbolAddress((void**)&k,    g_k);
    cudaGetSymbolAddress((void**)&v,    g_v);
    cudaGetSymbolAddress((void**)&ao,   g_ao);
    cudaGetSymbolAddress((void**)&attn, g_attn);

    const size_t sX = (size_t)C_DIM * AREA;     // per-batch feature map
    const size_t sA = (size_t)AREA * AREA;      // per-batch attn matrix

    groupnorm_kernel<<<BATCH * GROUPS, 256>>>(net, gns, gnb, xn);

    dim3 blk(256);
    dim3 gProj(AREA / 128, C_DIM / 128, BATCH);   // (32, 4, 4)
    // Q/K/V: W[o,c] @ xn[c,a] + b
    gemm128<0, 0><<<gProj, blk>>>(wq, xn, q, C_DIM, AREA, C_DIM, 0, sX, sX, 1.f, bq, nullptr, 0);
    gemm128<0, 0><<<gProj, blk>>>(wk, xn, k, C_DIM, AREA, C_DIM, 0, sX, sX, 1.f, bk, nullptr, 0);
    gemm128<0, 0><<<gProj, blk>>>(wv, xn, v, C_DIM, AREA, C_DIM, 0, sX, sX, 1.f, bv, nullptr, 0);

    // attn[i,j] = scale * sum_c q[c,i] * k[c,j]   (TN)
    dim3 gAttn(AREA / 128, AREA / 128, BATCH);    // (32, 32, 4)
    const float scale = 0.044194173824159216f;    // 512^-0.5
    gemm128<1, 0><<<gAttn, blk>>>(q, k, attn, AREA, AREA, C_DIM, sX, sX, sA, scale,
                                  nullptr, nullptr, 0);

    softmax4096<<<BATCH * AREA, 256>>>(attn);

    // ao[c,i] = sum_j v[c,j] * p[i,j]   (NT)
    gemm128<0, 1><<<gProj, blk>>>(v, attn, ao, C_DIM, AREA, AREA, sX, sA, sX, 1.f,
                                  nullptr, nullptr, 0);

    // out = net + Wo @ ao + bo
    gemm128<0, 0><<<gProj, blk>>>(wo, ao, out, C_DIM, AREA, C_DIM, 0, sX, sX, 1.f,
                                  bo, net, sX);
}

// round 10
// speedup vs baseline: 3.0066x; 3.0066x over previous
#include <cuda_runtime.h>
#include <math.h>
#include <stdint.h>

#define C_DIM 512
#define AREA  4096
#define BATCH 4
#define GROUPS 32
#define CPG   16
#define GRP_F4 16384   // (CPG*AREA)/4 float4s per group

// ---------------- scratch (static device globals; no allocation) ----------------
__device__ float g_xn  [(size_t)BATCH * C_DIM * AREA];
__device__ float g_q   [(size_t)BATCH * C_DIM * AREA];
__device__ float g_k   [(size_t)BATCH * C_DIM * AREA];
__device__ float g_v   [(size_t)BATCH * C_DIM * AREA];
__device__ float g_ao  [(size_t)BATCH * C_DIM * AREA];
__device__ float g_attn[(size_t)BATCH * AREA * AREA];

// ---------------- GroupNorm ----------------
__global__ void groupnorm_kernel(const float* __restrict__ net,
                                 const float* __restrict__ gscale,
                                 const float* __restrict__ gbias,
                                 float* __restrict__ xn) {
    const int bg = blockIdx.x;          // 0..127
    const int b  = bg >> 5;
    const int g  = bg & 31;
    const size_t base = ((size_t)b * C_DIM + (size_t)g * CPG) * AREA;
    const float4* src4 = (const float4*)(net + base);
    float4* dst4 = (float4*)(xn + base);
    const int tid = threadIdx.x;

    float s = 0.f, ss = 0.f;
    for (int i = tid; i < GRP_F4; i += 256) {
        float4 v = src4[i];
        s  += v.x + v.y + v.z + v.w;
        ss += v.x*v.x + v.y*v.y + v.z*v.z + v.w*v.w;
    }
    __shared__ float red[512];
    red[tid] = s; red[256 + tid] = ss;
    __syncthreads();
    for (int off = 128; off > 0; off >>= 1) {
        if (tid < off) {
            red[tid]       += red[tid + off];
            red[256 + tid] += red[256 + tid + off];
        }
        __syncthreads();
    }
    const float inv_n = 1.0f / 65536.0f;
    const float mu   = red[0] * inv_n;
    const float var  = red[256] * inv_n - mu * mu;
    const float rstd = rsqrtf(var + 1e-6f);

    for (int i = tid; i < GRP_F4; i += 256) {
        const int c_local = i >> 10;
        const float sc = gscale[g * CPG + c_local] * rstd;
        const float bi = gbias[g * CPG + c_local];
        float4 v = src4[i];
        v.x = (v.x - mu) * sc + bi;
        v.y = (v.y - mu) * sc + bi;
        v.z = (v.z - mu) * sc + bi;
        v.w = (v.w - mu) * sc + bi;
        dst4[i] = v;
    }
}

// ---------------- tf32 helpers ----------------
__device__ __forceinline__ uint32_t f2tf(float x) {
    uint32_t r;
    asm("cvt.rna.tf32.f32 %0, %1;" : "=r"(r) : "f"(x));
    return r;
}

__device__ __forceinline__ void mma8(float* c, const uint32_t* a, const uint32_t* b) {
    asm volatile("mma.sync.aligned.m16n8k8.row.col.f32.tf32.tf32.f32 "
                 "{%0,%1,%2,%3}, {%4,%5,%6,%7}, {%8,%9}, {%0,%1,%2,%3};\n"
                 : "+f"(c[0]), "+f"(c[1]), "+f"(c[2]), "+f"(c[3])
                 : "r"(a[0]), "r"(a[1]), "r"(a[2]), "r"(a[3]),
                   "r"(b[0]), "r"(b[1]));
}

// ---------------- tensor-core tf32 GEMM ----------------
// C[m,n] = alpha * sum_k Aval(m,k)*Bval(k,n) + bias[m] + resid[m,n]
// TA=0: A row-major [M,K] (K-contiguous) ; TA=1: A stored [K,M] (M-contiguous)
// TB=0: B row-major [K,N] (N-contiguous) ; TB=1: B stored [N,K] (K-contiguous)
// Block 128x128, BK=32, 256 threads (8 warps of 64x32), mma m16n8k8 tf32.
// Smem layouts (bank-conflict-free for both fill and fragment loads):
//   K-contiguous operand  -> [row][k]  stride 36
//   MN-contiguous operand -> [k][col]  stride 136
template<int TA, int TB>
__global__ __launch_bounds__(256, 2)
void gemm_tc(const float* __restrict__ A, const float* __restrict__ B,
             float* __restrict__ C,
             int M, int N, int K,
             size_t sAb, size_t sBb, size_t sCb,
             float alpha,
             const float* __restrict__ bias,
             const float* __restrict__ resid, size_t sRb) {
    __shared__ uint32_t As[4608];   // max(128*36, 32*136)
    __shared__ uint32_t Bs[4608];

    const int tid  = threadIdx.x;
    const int warp = tid >> 5;
    const int lane = tid & 31;
    const int g    = lane >> 2;     // 0..7
    const int tg   = lane & 3;      // 0..3
    const int warpM = warp >> 2;    // 0..1  (64 rows each)
    const int warpN = warp & 3;     // 0..3  (32 cols each)
    const int n0 = blockIdx.x * 128;
    const int m0 = blockIdx.y * 128;
    const int bz = blockIdx.z;

    const float* Ab = A + (size_t)bz * sAb;
    const float* Bb = B + (size_t)bz * sBb;
    const int K4 = K >> 2, N4 = N >> 2, M4 = M >> 2;

    float acc[4][4][4];
    #pragma unroll
    for (int mt = 0; mt < 4; ++mt)
        #pragma unroll
        for (int nt = 0; nt < 4; ++nt)
            #pragma unroll
            for (int r = 0; r < 4; ++r) acc[mt][nt][r] = 0.f;

    for (int k0 = 0; k0 < K; k0 += 32) {
        // ---- fill A ----
        if (TA == 0) {
            #pragma unroll
            for (int j = 0; j < 4; ++j) {
                const int l4  = j * 256 + tid;
                const int kk4 = l4 & 7, mm = l4 >> 3;
                float4 v = ((const float4*)Ab)[(size_t)(m0 + mm) * K4 + (k0 >> 2) + kk4];
                uint32_t* d = &As[mm * 36 + kk4 * 4];
                d[0] = f2tf(v.x); d[1] = f2tf(v.y); d[2] = f2tf(v.z); d[3] = f2tf(v.w);
            }
        } else {
            #pragma unroll
            for (int j = 0; j < 4; ++j) {
                const int l4  = j * 256 + tid;
                const int mm4 = l4 & 31, kk = l4 >> 5;
                float4 v = ((const float4*)Ab)[(size_t)(k0 + kk) * M4 + (m0 >> 2) + mm4];
                uint32_t* d = &As[kk * 136 + mm4 * 4];
                d[0] = f2tf(v.x); d[1] = f2tf(v.y); d[2] = f2tf(v.z); d[3] = f2tf(v.w);
            }
        }
        // ---- fill B ----
        if (TB == 0) {
            #pragma unroll
            for (int j = 0; j < 4; ++j) {
                const int l4  = j * 256 + tid;
                const int nn4 = l4 & 31, kk = l4 >> 5;
                float4 v = ((const float4*)Bb)[(size_t)(k0 + kk) * N4 + (n0 >> 2) + nn4];
                uint32_t* d = &Bs[kk * 136 + nn4 * 4];
                d[0] = f2tf(v.x); d[1] = f2tf(v.y); d[2] = f2tf(v.z); d[3] = f2tf(v.w);
            }
        } else {
            #pragma unroll
            for (int j = 0; j < 4; ++j) {
                const int l4  = j * 256 + tid;
                const int kk4 = l4 & 7, nn = l4 >> 3;
                float4 v = ((const float4*)Bb)[(size_t)(n0 + nn) * K4 + (k0 >> 2) + kk4];
                uint32_t* d = &Bs[nn * 36 + kk4 * 4];
                d[0] = f2tf(v.x); d[1] = f2tf(v.y); d[2] = f2tf(v.z); d[3] = f2tf(v.w);
            }
        }
        __syncthreads();

        #pragma unroll
        for (int ks = 0; ks < 4; ++ks) {
            const int kb = ks * 8;
            uint32_t af[4][4], bf[4][2];
            #pragma unroll
            for (int mt = 0; mt < 4; ++mt) {
                const int mb = warpM * 64 + mt * 16;
                if (TA == 0) {
                    af[mt][0] = As[(mb + g) * 36     + kb + tg];
                    af[mt][1] = As[(mb + g + 8) * 36 + kb + tg];
                    af[mt][2] = As[(mb + g) * 36     + kb + tg + 4];
                    af[mt][3] = As[(mb + g + 8) * 36 + kb + tg + 4];
                } else {
                    af[mt][0] = As[(kb + tg) * 136     + mb + g];
                    af[mt][1] = As[(kb + tg) * 136     + mb + g + 8];
                    af[mt][2] = As[(kb + tg + 4) * 136 + mb + g];
                    af[mt][3] = As[(kb + tg + 4) * 136 + mb + g + 8];
                }
            }
            #pragma unroll
            for (int nt = 0; nt < 4; ++nt) {
                const int nb = warpN * 32 + nt * 8;
                if (TB == 0) {
                    bf[nt][0] = Bs[(kb + tg) * 136     + nb + g];
                    bf[nt][1] = Bs[(kb + tg + 4) * 136 + nb + g];
                } else {
                    bf[nt][0] = Bs[(nb + g) * 36 + kb + tg];
                    bf[nt][1] = Bs[(nb + g) * 36 + kb + tg + 4];
                }
            }
            #pragma unroll
            for (int mt = 0; mt < 4; ++mt)
                #pragma unroll
                for (int nt = 0; nt < 4; ++nt)
                    mma8(acc[mt][nt], af[mt], bf[nt]);
        }
        __syncthreads();
    }

    // ---- epilogue ----
    float* Cb = C + (size_t)bz * sCb;
    const float* Rb = resid ? (resid + (size_t)bz * sRb) : nullptr;

    #pragma unroll
    for (int mt = 0; mt < 4; ++mt) {
        const int mb = m0 + warpM * 64 + mt * 16;
        const int r0 = mb + g, r1 = mb + g + 8;
        const float bi0 = bias ? bias[r0] : 0.f;
        const float bi1 = bias ? bias[r1] : 0.f;
        #pragma unroll
        for (int nt = 0; nt < 4; ++nt) {
            const int nn = n0 + warpN * 32 + nt * 8 + 2 * tg;
            const size_t o0 = (size_t)r0 * N + nn;
            const size_t o1 = (size_t)r1 * N + nn;
            float2 v0 = { alpha * acc[mt][nt][0] + bi0, alpha * acc[mt][nt][1] + bi0 };
            float2 v1 = { alpha * acc[mt][nt][2] + bi1, alpha * acc[mt][nt][3] + bi1 };
            if (Rb) {
                v0.x += Rb[o0]; v0.y += Rb[o0 + 1];
                v1.x += Rb[o1]; v1.y += Rb[o1 + 1];
            }
            *(float2*)&Cb[o0] = v0;
            *(float2*)&Cb[o1] = v1;
        }
    }
}

// ---------------- softmax over rows of length 4096 ----------------
__global__ void softmax4096(float* __restrict__ attn) {
    const size_t row = blockIdx.x;
    float* p = attn + row * AREA;
    const int tid = threadIdx.x;

    float4 r[4];
    #pragma unroll
    for (int i = 0; i < 4; ++i)
        r[i] = *(const float4*)&p[(tid + i * 256) * 4];

    float m = -3.0e38f;
    #pragma unroll
    for (int i = 0; i < 4; ++i)
        m = fmaxf(m, fmaxf(fmaxf(r[i].x, r[i].y), fmaxf(r[i].z, r[i].w)));
    __shared__ float red[256];
    red[tid] = m; __syncthreads();
    for (int off = 128; off > 0; off >>= 1) {
        if (tid < off) red[tid] = fmaxf(red[tid], red[tid + off]);
        __syncthreads();
    }
    m = red[0];
    __syncthreads();

    float s = 0.f;
    #pragma unroll
    for (int i = 0; i < 4; ++i) {
        r[i].x = __expf(r[i].x - m); r[i].y = __expf(r[i].y - m);
        r[i].z = __expf(r[i].z - m); r[i].w = __expf(r[i].w - m);
        s += r[i].x + r[i].y + r[i].z + r[i].w;
    }
    red[tid] = s; __syncthreads();
    for (int off = 128; off > 0; off >>= 1) {
        if (tid < off) red[tid] += red[tid + off];
        __syncthreads();
    }
    const float inv = 1.0f / red[0];

    #pragma unroll
    for (int i = 0; i < 4; ++i) {
        r[i].x *= inv; r[i].y *= inv; r[i].z *= inv; r[i].w *= inv;
        *(float4*)&p[(tid + i * 256) * 4] = r[i];
    }
}

// ---------------- launch ----------------
extern "C" void kernel_launch(void* const* d_in, const int* in_sizes, int n_in,
                              void* d_out, int out_size) {
    const float* net = (const float*)d_in[0];
    const float* gns = (const float*)d_in[1];
    const float* gnb = (const float*)d_in[2];
    const float* wq  = (const float*)d_in[3];
    const float* bq  = (const float*)d_in[4];
    const float* wk  = (const float*)d_in[5];
    const float* bk  = (const float*)d_in[6];
    const float* wv  = (const float*)d_in[7];
    const float* bv  = (const float*)d_in[8];
    const float* wo  = (const float*)d_in[9];
    const float* bo  = (const float*)d_in[10];
    float* out = (float*)d_out;

    float *xn, *q, *k, *v, *ao, *attn;
    cudaGetSymbolAddress((void**)&xn,   g_xn);
    cudaGetSymbolAddress((void**)&q,    g_q);
    cudaGetSymbolAddress((void**)&k,    g_k);
    cudaGetSymbolAddress((void**)&v,    g_v);
    cudaGetSymbolAddress((void**)&ao,   g_ao);
    cudaGetSymbolAddress((void**)&attn, g_attn);

    const size_t sX = (size_t)C_DIM * AREA;
    const size_t sA = (size_t)AREA * AREA;

    groupnorm_kernel<<<BATCH * GROUPS, 256>>>(net, gns, gnb, xn);

    dim3 blk(256);
    dim3 gProj(AREA / 128, C_DIM / 128, BATCH);   // (32, 4, 4)
    // Q/K/V: W[o,c] @ xn[c,a] + b   (A row-major, B N-contiguous)
    gemm_tc<0, 0><<<gProj, blk>>>(wq, xn, q, C_DIM, AREA, C_DIM, 0, sX, sX, 1.f, bq, nullptr, 0);
    gemm_tc<0, 0><<<gProj, blk>>>(wk, xn, k, C_DIM, AREA, C_DIM, 0, sX, sX, 1.f, bk, nullptr, 0);
    gemm_tc<0, 0><<<gProj, blk>>>(wv, xn, v, C_DIM, AREA, C_DIM, 0, sX, sX, 1.f, bv, nullptr, 0);

    // attn[i,j] = scale * sum_c q[c,i] * k[c,j]   (TN: A stored [K,M])
    dim3 gAttn(AREA / 128, AREA / 128, BATCH);    // (32, 32, 4)
    const float scale = 0.044194173824159216f;    // 512^-0.5
    gemm_tc<1, 0><<<gAttn, blk>>>(q, k, attn, AREA, AREA, C_DIM, sX, sX, sA, scale,
                                  nullptr, nullptr, 0);

    softmax4096<<<BATCH * AREA, 256>>>(attn);

    // ao[c,i] = sum_j v[c,j] * p[i,j]   (NT: B stored [N,K])
    gemm_tc<0, 1><<<gProj, blk>>>(v, attn, ao, C_DIM, AREA, AREA, sX, sA, sX, 1.f,
                                  nullptr, nullptr, 0);

    // out = net + Wo @ ao + bo
    gemm_tc<0, 0><<<gProj, blk>>>(wo, ao, out, C_DIM, AREA, C_DIM, 0, sX, sX, 1.f,
                                  bo, net, sX);
}